// round 1
// baseline (speedup 1.0000x reference)
#include <cuda_runtime.h>
#include <cstdint>

// ---------------------------------------------------------------------------
// FocalLoss (RetinaNet): B=8 images, A=65536 anchors, C=80 classes, M=32 GT.
// Strategy: HBM-bound on classifications (167.8 MB). Three kernels:
//   1) assign_kernel: per-anchor IoU vs 32 GT boxes -> 1-byte code
//      (0..79 = positive w/ label, 128 = negative, 255 = ignore),
//      plus smooth-L1 regression loss for positives and num_pos count.
//   2) cls_kernel: stream classifications as float4 (coalesced), focal loss.
//   3) finalize_kernel: per-image normalization + batch mean -> d_out[2].
// Scratch in __device__ globals (no allocation); zeroed per launch.
// ---------------------------------------------------------------------------

#define MAX_B  8
#define MAX_BA (8 * 65536)

__device__ double        g_cls_sum[MAX_B];
__device__ double        g_reg_sum[MAX_B];
__device__ int           g_pos_cnt[MAX_B];
__device__ unsigned char g_meta[MAX_BA];

__global__ void zero_kernel(int B) {
    int i = threadIdx.x;
    if (i < B) {
        g_cls_sum[i] = 0.0;
        g_reg_sum[i] = 0.0;
        g_pos_cnt[i] = 0;
    }
}

// ---------------------------------------------------------------------------
// Kernel 1: anchor assignment + regression loss + positive count
// grid: (ceil(A/256), B), block: 256
// ---------------------------------------------------------------------------
__global__ void assign_kernel(const float* __restrict__ anchors,      // [A,4]
                              const float* __restrict__ regressions,  // [B,A,4]
                              const float* __restrict__ annotations,  // [B,M,5]
                              int A, int M)
{
    const int b   = blockIdx.y;
    const int a   = blockIdx.x * blockDim.x + threadIdx.x;
    const int tid = threadIdx.x;

    __shared__ float s_ann[32 * 5];
    __shared__ float s_area[32];

    if (tid < M * 5) s_ann[tid] = annotations[(size_t)b * M * 5 + tid];
    __syncthreads();
    if (tid < M) {
        float x1 = s_ann[tid * 5 + 0], y1 = s_ann[tid * 5 + 1];
        float x2 = s_ann[tid * 5 + 2], y2 = s_ann[tid * 5 + 3];
        s_area[tid] = (x2 - x1) * (y2 - y1);
    }
    __syncthreads();

    float regsum = 0.0f;
    int   posflag = 0;

    if (a < A) {
        float4 an = reinterpret_cast<const float4*>(anchors)[a];
        float aw = an.z - an.x;
        float ah = an.w - an.y;
        float area_a = aw * ah;

        float best = -1.0f;
        int   bi   = 0;
        #pragma unroll 8
        for (int m = 0; m < M; m++) {
            float bx1 = s_ann[m * 5 + 0], by1 = s_ann[m * 5 + 1];
            float bx2 = s_ann[m * 5 + 2], by2 = s_ann[m * 5 + 3];
            float iw = fminf(an.z, bx2) - fmaxf(an.x, bx1);
            float ih = fminf(an.w, by2) - fmaxf(an.y, by1);
            iw = fmaxf(iw, 0.0f);
            ih = fmaxf(ih, 0.0f);
            float inter = iw * ih;
            float ua    = fmaxf(area_a + s_area[m] - inter, 1e-8f);
            float iou   = inter / ua;
            if (iou > best) { best = iou; bi = m; }   // first-max (jnp.argmax)
        }

        bool pos = (best >= 0.5f);
        unsigned char code;
        if (pos)                  code = (unsigned char)(int)s_ann[bi * 5 + 4];
        else if (best < 0.4f)     code = 128;  // negative
        else                      code = 255;  // ignore
        g_meta[(size_t)b * A + a] = code;

        if (pos) {
            posflag = 1;
            float gx1 = s_ann[bi * 5 + 0], gy1 = s_ann[bi * 5 + 1];
            float gx2 = s_ann[bi * 5 + 2], gy2 = s_ann[bi * 5 + 3];
            float gw = gx2 - gx1, gh = gy2 - gy1;
            float gcx = gx1 + 0.5f * gw, gcy = gy1 + 0.5f * gh;  // unclamped ctr
            gw = fmaxf(gw, 1.0f);
            gh = fmaxf(gh, 1.0f);
            float acx = an.x + 0.5f * aw, acy = an.y + 0.5f * ah;
            // targets / [0.1,0.1,0.2,0.2]
            float t0 = (gcx - acx) / aw * 10.0f;
            float t1 = (gcy - acy) / ah * 10.0f;
            float t2 = __logf(gw / aw) * 5.0f;
            float t3 = __logf(gh / ah) * 5.0f;

            float4 rg = reinterpret_cast<const float4*>(regressions)[(size_t)b * A + a];
            const float th = 1.0f / 9.0f;
            const float c2 = 0.5f / 9.0f;
            float d;
            d = fabsf(t0 - rg.x); regsum += (d <= th) ? 4.5f * d * d : d - c2;
            d = fabsf(t1 - rg.y); regsum += (d <= th) ? 4.5f * d * d : d - c2;
            d = fabsf(t2 - rg.z); regsum += (d <= th) ? 4.5f * d * d : d - c2;
            d = fabsf(t3 - rg.w); regsum += (d <= th) ? 4.5f * d * d : d - c2;
        }
    }

    // block reduce (regsum, posflag)
    #pragma unroll
    for (int off = 16; off > 0; off >>= 1) {
        regsum  += __shfl_down_sync(0xFFFFFFFFu, regsum, off);
        posflag += __shfl_down_sync(0xFFFFFFFFu, posflag, off);
    }
    __shared__ float sw_r[8];
    __shared__ int   sw_c[8];
    int lane = tid & 31, warp = tid >> 5;
    if (lane == 0) { sw_r[warp] = regsum; sw_c[warp] = posflag; }
    __syncthreads();
    if (warp == 0) {
        float r = (lane < 8) ? sw_r[lane] : 0.0f;
        int   c = (lane < 8) ? sw_c[lane] : 0;
        #pragma unroll
        for (int off = 4; off > 0; off >>= 1) {
            r += __shfl_down_sync(0xFFFFFFFFu, r, off);
            c += __shfl_down_sync(0xFFFFFFFFu, c, off);
        }
        if (lane == 0) {
            if (r != 0.0f) atomicAdd(&g_reg_sum[b], (double)r);
            if (c != 0)    atomicAdd(&g_pos_cnt[b], c);
        }
    }
}

// ---------------------------------------------------------------------------
// Kernel 2: focal classification loss, streaming float4 over [A*C] per image
// grid: (ceil(A*C/4/256), B), block: 256
// ---------------------------------------------------------------------------
__global__ void cls_kernel(const float* __restrict__ cls, int A, int C)
{
    const int b   = blockIdx.y;
    const int idx = blockIdx.x * blockDim.x + threadIdx.x;
    const int AC4 = (A * C) >> 2;

    float sum = 0.0f;
    if (idx < AC4) {
        int o  = idx << 2;          // element offset within image (mult of 4)
        int a  = o / C;             // C=80: 4 classes always inside one anchor
        int c0 = o - a * C;
        unsigned char code = g_meta[(size_t)b * A + a];
        if (code != 255) {          // 255 = ignore -> zero contribution
            float4 v = reinterpret_cast<const float4*>(cls + (size_t)b * A * C)[idx];
            float vv[4] = { v.x, v.y, v.z, v.w };
            #pragma unroll
            for (int j = 0; j < 4; j++) {
                float p = fminf(fmaxf(vv[j], 1e-4f), 1.0f - 1e-4f);
                bool one = (code == (unsigned char)(c0 + j));  // pos anchors only: code<80
                float l;
                if (one) { float q = 1.0f - p; l = 0.5f * q * q * (-__logf(p)); }
                else     {                     l = 0.5f * p * p * (-__logf(1.0f - p)); }
                sum += l;
            }
        }
    }

    #pragma unroll
    for (int off = 16; off > 0; off >>= 1)
        sum += __shfl_down_sync(0xFFFFFFFFu, sum, off);
    __shared__ float sw[8];
    int lane = threadIdx.x & 31, warp = threadIdx.x >> 5;
    if (lane == 0) sw[warp] = sum;
    __syncthreads();
    if (warp == 0) {
        float s = (lane < 8) ? sw[lane] : 0.0f;
        #pragma unroll
        for (int off = 4; off > 0; off >>= 1)
            s += __shfl_down_sync(0xFFFFFFFFu, s, off);
        if (lane == 0) atomicAdd(&g_cls_sum[b], (double)s);
    }
}

// ---------------------------------------------------------------------------
// Kernel 3: normalize per image, mean over batch, write out[0]=cls, out[1]=reg
// ---------------------------------------------------------------------------
__global__ void finalize_kernel(float* __restrict__ out, int B)
{
    if (threadIdx.x == 0 && blockIdx.x == 0) {
        double cm = 0.0, rm = 0.0;
        for (int b = 0; b < B; b++) {
            double np = (double)g_pos_cnt[b];
            cm += g_cls_sum[b] / fmax(np, 1.0);
            if (g_pos_cnt[b] > 0)
                rm += g_reg_sum[b] / fmax(np * 4.0, 1.0);
        }
        out[0] = (float)(cm / (double)B);
        out[1] = (float)(rm / (double)B);
    }
}

// ---------------------------------------------------------------------------
extern "C" void kernel_launch(void* const* d_in, const int* in_sizes, int n_in,
                              void* d_out, int out_size)
{
    const float* classifications = (const float*)d_in[0];  // [B,A,C]
    const float* regressions     = (const float*)d_in[1];  // [B,A,4]
    const float* anchors         = (const float*)d_in[2];  // [1,A,4]
    const float* annotations     = (const float*)d_in[3];  // [B,M,5]
    float* out = (float*)d_out;

    const int A = in_sizes[2] / 4;
    const int B = in_sizes[1] / (4 * A);
    const int C = in_sizes[0] / (B * A);
    const int M = in_sizes[3] / (5 * B);

    zero_kernel<<<1, 32>>>(B);

    {
        dim3 grid((A + 255) / 256, B);
        assign_kernel<<<grid, 256>>>(anchors, regressions, annotations, A, M);
    }
    {
        int ac4 = (A * C) / 4;
        dim3 grid((ac4 + 255) / 256, B);
        cls_kernel<<<grid, 256>>>(classifications, A, C);
    }
    finalize_kernel<<<1, 32>>>(out, B);
    (void)n_in; (void)out_size;
}

// round 2
// speedup vs baseline: 1.3383x; 1.3383x over previous
#include <cuda_runtime.h>
#include <cstdint>

// ---------------------------------------------------------------------------
// FocalLoss (RetinaNet): B=8 images, A=65536 anchors, C=80 classes, M=32 GT.
// HBM-bound on classifications (167.8 MB). Four launches:
//   0) zero_kernel: reset accumulators
//   1) assign_kernel: per-anchor IoU vs GT -> 1-byte code
//      (0..79 = positive label, 128 = negative, 255 = ignore),
//      + smooth-L1 regression loss + positive count.
//   2) cls_kernel: grid-stride float4 stream over classifications, focal loss.
//      ~40 float4/thread, 128 blocks/image -> few atomics, high MLP.
//   3) finalize_kernel: warp-parallel normalization + batch mean -> d_out[2].
// ---------------------------------------------------------------------------

#define MAX_B  8
#define MAX_BA (8 * 65536)

__device__ double        g_cls_sum[MAX_B];
__device__ double        g_reg_sum[MAX_B];
__device__ int           g_pos_cnt[MAX_B];
__device__ unsigned char g_meta[MAX_BA];

__global__ void zero_kernel(int B) {
    int i = threadIdx.x;
    if (i < B) {
        g_cls_sum[i] = 0.0;
        g_reg_sum[i] = 0.0;
        g_pos_cnt[i] = 0;
    }
}

// ---------------------------------------------------------------------------
// Kernel 1: anchor assignment + regression loss + positive count
// grid: (ceil(A/256), B), block: 256
// ---------------------------------------------------------------------------
__global__ void assign_kernel(const float* __restrict__ anchors,      // [A,4]
                              const float* __restrict__ regressions,  // [B,A,4]
                              const float* __restrict__ annotations,  // [B,M,5]
                              int A, int M)
{
    const int b   = blockIdx.y;
    const int a   = blockIdx.x * blockDim.x + threadIdx.x;
    const int tid = threadIdx.x;

    __shared__ float s_ann[32 * 5];
    __shared__ float s_area[32];

    if (tid < M * 5) s_ann[tid] = annotations[(size_t)b * M * 5 + tid];
    __syncthreads();
    if (tid < M) {
        float x1 = s_ann[tid * 5 + 0], y1 = s_ann[tid * 5 + 1];
        float x2 = s_ann[tid * 5 + 2], y2 = s_ann[tid * 5 + 3];
        s_area[tid] = (x2 - x1) * (y2 - y1);
    }
    __syncthreads();

    float regsum = 0.0f;
    int   posflag = 0;

    if (a < A) {
        float4 an = reinterpret_cast<const float4*>(anchors)[a];
        float aw = an.z - an.x;
        float ah = an.w - an.y;
        float area_a = aw * ah;

        float best = -1.0f;
        int   bi   = 0;
        #pragma unroll 8
        for (int m = 0; m < M; m++) {
            float bx1 = s_ann[m * 5 + 0], by1 = s_ann[m * 5 + 1];
            float bx2 = s_ann[m * 5 + 2], by2 = s_ann[m * 5 + 3];
            float iw = fminf(an.z, bx2) - fmaxf(an.x, bx1);
            float ih = fminf(an.w, by2) - fmaxf(an.y, by1);
            iw = fmaxf(iw, 0.0f);
            ih = fmaxf(ih, 0.0f);
            float inter = iw * ih;
            float ua    = fmaxf(area_a + s_area[m] - inter, 1e-8f);
            float iou   = inter / ua;
            if (iou > best) { best = iou; bi = m; }   // first-max (jnp.argmax)
        }

        bool pos = (best >= 0.5f);
        unsigned char code;
        if (pos)                  code = (unsigned char)(int)s_ann[bi * 5 + 4];
        else if (best < 0.4f)     code = 128;  // negative
        else                      code = 255;  // ignore
        g_meta[(size_t)b * A + a] = code;

        if (pos) {
            posflag = 1;
            float gx1 = s_ann[bi * 5 + 0], gy1 = s_ann[bi * 5 + 1];
            float gx2 = s_ann[bi * 5 + 2], gy2 = s_ann[bi * 5 + 3];
            float gw = gx2 - gx1, gh = gy2 - gy1;
            float gcx = gx1 + 0.5f * gw, gcy = gy1 + 0.5f * gh;  // unclamped ctr
            gw = fmaxf(gw, 1.0f);
            gh = fmaxf(gh, 1.0f);
            float acx = an.x + 0.5f * aw, acy = an.y + 0.5f * ah;
            // targets / [0.1,0.1,0.2,0.2]
            float t0 = (gcx - acx) / aw * 10.0f;
            float t1 = (gcy - acy) / ah * 10.0f;
            float t2 = __logf(gw / aw) * 5.0f;
            float t3 = __logf(gh / ah) * 5.0f;

            float4 rg = reinterpret_cast<const float4*>(regressions)[(size_t)b * A + a];
            const float th = 1.0f / 9.0f;
            const float c2 = 0.5f / 9.0f;
            float d;
            d = fabsf(t0 - rg.x); regsum += (d <= th) ? 4.5f * d * d : d - c2;
            d = fabsf(t1 - rg.y); regsum += (d <= th) ? 4.5f * d * d : d - c2;
            d = fabsf(t2 - rg.z); regsum += (d <= th) ? 4.5f * d * d : d - c2;
            d = fabsf(t3 - rg.w); regsum += (d <= th) ? 4.5f * d * d : d - c2;
        }
    }

    // block reduce (regsum, posflag)
    #pragma unroll
    for (int off = 16; off > 0; off >>= 1) {
        regsum  += __shfl_down_sync(0xFFFFFFFFu, regsum, off);
        posflag += __shfl_down_sync(0xFFFFFFFFu, posflag, off);
    }
    __shared__ float sw_r[8];
    __shared__ int   sw_c[8];
    int lane = tid & 31, warp = tid >> 5;
    if (lane == 0) { sw_r[warp] = regsum; sw_c[warp] = posflag; }
    __syncthreads();
    if (warp == 0) {
        float r = (lane < 8) ? sw_r[lane] : 0.0f;
        int   c = (lane < 8) ? sw_c[lane] : 0;
        #pragma unroll
        for (int off = 4; off > 0; off >>= 1) {
            r += __shfl_down_sync(0xFFFFFFFFu, r, off);
            c += __shfl_down_sync(0xFFFFFFFFu, c, off);
        }
        if (lane == 0) {
            if (r != 0.0f) atomicAdd(&g_reg_sum[b], (double)r);
            if (c != 0)    atomicAdd(&g_pos_cnt[b], c);
        }
    }
}

// ---------------------------------------------------------------------------
// Kernel 2: focal classification loss. Grid-stride over float4s of one image.
// grid: (BLK_X, B), block: 256.  Few blocks => few atomics; coalesced stride.
// ---------------------------------------------------------------------------
template<int CC>
__device__ __forceinline__ float cls_body(const float4* __restrict__ base,
                                          const unsigned char* __restrict__ meta,
                                          int AC4, int stride, int start)
{
    float sum = 0.0f;
    for (int idx = start; idx < AC4; idx += stride) {
        int o  = idx << 2;
        int a  = o / CC;            // compile-time C -> mul/shift
        int c0 = o - a * CC;
        unsigned char code = meta[a];
        float4 v = base[idx];
        if (code != 255) {          // 255 = ignore -> zero contribution
            float vv[4] = { v.x, v.y, v.z, v.w };
            #pragma unroll
            for (int j = 0; j < 4; j++) {
                float p = fminf(fmaxf(vv[j], 1e-4f), 1.0f - 1e-4f);
                bool one = (code == (unsigned char)(c0 + j));  // pos only: code<80
                if (one) { float q = 1.0f - p; sum += 0.5f * q * q * (-__logf(p)); }
                else     {                     sum += 0.5f * p * p * (-__logf(1.0f - p)); }
            }
        }
    }
    return sum;
}

__global__ void cls_kernel(const float* __restrict__ cls, int A, int C)
{
    const int b      = blockIdx.y;
    const int AC4    = (A * C) >> 2;
    const int stride = gridDim.x * blockDim.x;
    const int start  = blockIdx.x * blockDim.x + threadIdx.x;

    const float4* base = reinterpret_cast<const float4*>(cls + (size_t)b * A * C);
    const unsigned char* meta = g_meta + (size_t)b * A;

    float sum;
    if (C == 80) sum = cls_body<80>(base, meta, AC4, stride, start);
    else {
        sum = 0.0f;
        for (int idx = start; idx < AC4; idx += stride) {
            int o  = idx << 2;
            int a  = o / C;
            int c0 = o - a * C;
            unsigned char code = meta[a];
            float4 v = base[idx];
            if (code != 255) {
                float vv[4] = { v.x, v.y, v.z, v.w };
                #pragma unroll
                for (int j = 0; j < 4; j++) {
                    float p = fminf(fmaxf(vv[j], 1e-4f), 1.0f - 1e-4f);
                    bool one = (code == (unsigned char)(c0 + j));
                    if (one) { float q = 1.0f - p; sum += 0.5f * q * q * (-__logf(p)); }
                    else     {                     sum += 0.5f * p * p * (-__logf(1.0f - p)); }
                }
            }
        }
    }

    // block reduce
    #pragma unroll
    for (int off = 16; off > 0; off >>= 1)
        sum += __shfl_down_sync(0xFFFFFFFFu, sum, off);
    __shared__ float sw[8];
    int lane = threadIdx.x & 31, warp = threadIdx.x >> 5;
    if (lane == 0) sw[warp] = sum;
    __syncthreads();
    if (warp == 0) {
        float s = (lane < 8) ? sw[lane] : 0.0f;
        #pragma unroll
        for (int off = 4; off > 0; off >>= 1)
            s += __shfl_down_sync(0xFFFFFFFFu, s, off);
        if (lane == 0) atomicAdd(&g_cls_sum[b], (double)s);
    }
}

// ---------------------------------------------------------------------------
// Kernel 3: warp-parallel normalization + batch mean, write out[0..1]
// ---------------------------------------------------------------------------
__global__ void finalize_kernel(float* __restrict__ out, int B)
{
    int lane = threadIdx.x;
    double cm = 0.0, rm = 0.0;
    if (lane < B) {
        double np = (double)g_pos_cnt[lane];
        cm = g_cls_sum[lane] / fmax(np, 1.0);
        rm = (g_pos_cnt[lane] > 0) ? g_reg_sum[lane] / fmax(np * 4.0, 1.0) : 0.0;
    }
    #pragma unroll
    for (int off = 16; off > 0; off >>= 1) {
        cm += __shfl_down_sync(0xFFFFFFFFu, cm, off);
        rm += __shfl_down_sync(0xFFFFFFFFu, rm, off);
    }
    if (lane == 0) {
        out[0] = (float)(cm / (double)B);
        out[1] = (float)(rm / (double)B);
    }
}

// ---------------------------------------------------------------------------
extern "C" void kernel_launch(void* const* d_in, const int* in_sizes, int n_in,
                              void* d_out, int out_size)
{
    const float* classifications = (const float*)d_in[0];  // [B,A,C]
    const float* regressions     = (const float*)d_in[1];  // [B,A,4]
    const float* anchors         = (const float*)d_in[2];  // [1,A,4]
    const float* annotations     = (const float*)d_in[3];  // [B,M,5]
    float* out = (float*)d_out;

    const int A = in_sizes[2] / 4;
    const int B = in_sizes[1] / (4 * A);
    const int C = in_sizes[0] / (B * A);
    const int M = in_sizes[3] / (5 * B);

    zero_kernel<<<1, 32>>>(B);

    {
        dim3 grid((A + 255) / 256, B);
        assign_kernel<<<grid, 256>>>(anchors, regressions, annotations, A, M);
    }
    {
        // 128 blocks/image x 8 images = 1024 blocks -> ~1770 threads/SM,
        // ~40 float4 per thread, coalesced grid-stride.
        dim3 grid(128, B);
        cls_kernel<<<grid, 256>>>(classifications, A, C);
    }
    finalize_kernel<<<1, 32>>>(out, B);
    (void)n_in; (void)out_size;
}

// round 3
// speedup vs baseline: 1.4706x; 1.0989x over previous
#include <cuda_runtime.h>
#include <cstdint>

// ---------------------------------------------------------------------------
// FocalLoss (RetinaNet), fully fused single kernel.
// B=8 images, A=65536 anchors, C=80 classes, M=32 GT.
//
// Grid: (A/ABLK, B) blocks, 256 threads. Each block owns ABLK=512 anchors of
// one image:
//   Phase A: IoU/argmax vs M GT boxes -> 1-byte code in SMEM
//            (0..C-1 = positive label, 128 = negative, 255 = ignore),
//            smooth-L1 reg loss + positive count for the slice.
//   Phase B: stream the slice's [ABLK, C] classifications as float4
//            (contiguous, coalesced), focal loss.
//   Reduce:  block reduce -> double atomics into per-image accumulators.
//   Last block (atomic ticket): normalize, batch-mean, write out[2],
//            reset accumulators to zero for the next graph replay.
// __device__ globals start zero-initialized; last block restores that
// invariant, so every launch (incl. graph replays) starts clean.
// ---------------------------------------------------------------------------

#define MAX_B   8
#define MAX_M   64
#define ABLK    512
#define NTHR    256

__device__ double g_cls_sum[MAX_B];
__device__ double g_reg_sum[MAX_B];
__device__ int    g_pos_cnt[MAX_B];
__device__ int    g_done;

// focal loss for 4 consecutive classes of one anchor
__device__ __forceinline__ float focal4(float4 v, unsigned char code, int c0)
{
    float vv[4] = { v.x, v.y, v.z, v.w };
    float s = 0.0f;
    #pragma unroll
    for (int j = 0; j < 4; j++) {
        float p = fminf(fmaxf(vv[j], 1e-4f), 1.0f - 1e-4f);
        bool one = (code == (unsigned char)(c0 + j));   // only pos codes < C match
        if (one) { float q = 1.0f - p; s += 0.5f * q * q * (-__logf(p)); }
        else     {                     s += 0.5f * p * p * (-__logf(1.0f - p)); }
    }
    return s;
}

__global__ void __launch_bounds__(NTHR)
focal_fused_kernel(const float* __restrict__ cls,         // [B,A,C]
                   const float* __restrict__ regressions, // [B,A,4]
                   const float* __restrict__ anchors,     // [A,4]
                   const float* __restrict__ annotations, // [B,M,5]
                   float* __restrict__ out,
                   int A, int C, int M, int B, int total_blocks)
{
    const int b   = blockIdx.y;
    const int a0  = blockIdx.x * ABLK;
    const int tid = threadIdx.x;
    const int aend = min(a0 + ABLK, A);
    const int nA   = aend - a0;

    __shared__ float         s_ann[MAX_M * 5];
    __shared__ float         s_area[MAX_M];
    __shared__ unsigned char s_code[ABLK];
    __shared__ float         sw_f[8];
    __shared__ int           sw_i[8];
    __shared__ int           s_last;

    // ---- load annotations ----
    for (int i = tid; i < M * 5; i += NTHR)
        s_ann[i] = annotations[(size_t)b * M * 5 + i];
    __syncthreads();
    if (tid < M) {
        float x1 = s_ann[tid * 5 + 0], y1 = s_ann[tid * 5 + 1];
        float x2 = s_ann[tid * 5 + 2], y2 = s_ann[tid * 5 + 3];
        s_area[tid] = (x2 - x1) * (y2 - y1);
    }
    __syncthreads();

    // ---- Phase A: assignment + regression loss for this slice ----
    float regsum = 0.0f;
    int   poscnt = 0;

    for (int la = tid; la < nA; la += NTHR) {
        const int a = a0 + la;
        float4 an = reinterpret_cast<const float4*>(anchors)[a];
        float aw = an.z - an.x;
        float ah = an.w - an.y;
        float area_a = aw * ah;

        float best = -1.0f;
        int   bi   = 0;
        #pragma unroll 8
        for (int m = 0; m < M; m++) {
            float bx1 = s_ann[m * 5 + 0], by1 = s_ann[m * 5 + 1];
            float bx2 = s_ann[m * 5 + 2], by2 = s_ann[m * 5 + 3];
            float iw = fmaxf(fminf(an.z, bx2) - fmaxf(an.x, bx1), 0.0f);
            float ih = fmaxf(fminf(an.w, by2) - fmaxf(an.y, by1), 0.0f);
            float inter = iw * ih;
            float ua    = fmaxf(area_a + s_area[m] - inter, 1e-8f);
            float iou   = inter / ua;
            if (iou > best) { best = iou; bi = m; }   // first-max (jnp.argmax)
        }

        bool pos = (best >= 0.5f);
        unsigned char code;
        if (pos)              code = (unsigned char)(int)s_ann[bi * 5 + 4];
        else if (best < 0.4f) code = 128;   // negative
        else                  code = 255;   // ignore
        s_code[la] = code;

        if (pos) {
            poscnt++;
            float gx1 = s_ann[bi * 5 + 0], gy1 = s_ann[bi * 5 + 1];
            float gx2 = s_ann[bi * 5 + 2], gy2 = s_ann[bi * 5 + 3];
            float gw = gx2 - gx1, gh = gy2 - gy1;
            float gcx = gx1 + 0.5f * gw, gcy = gy1 + 0.5f * gh;  // unclamped ctr
            gw = fmaxf(gw, 1.0f);
            gh = fmaxf(gh, 1.0f);
            float acx = an.x + 0.5f * aw, acy = an.y + 0.5f * ah;
            float t0 = (gcx - acx) / aw * 10.0f;   // / 0.1
            float t1 = (gcy - acy) / ah * 10.0f;
            float t2 = __logf(gw / aw) * 5.0f;     // / 0.2
            float t3 = __logf(gh / ah) * 5.0f;

            float4 rg = reinterpret_cast<const float4*>(regressions)[(size_t)b * A + a];
            const float th = 1.0f / 9.0f;
            const float c2 = 0.5f / 9.0f;
            float d;
            d = fabsf(t0 - rg.x); regsum += (d <= th) ? 4.5f * d * d : d - c2;
            d = fabsf(t1 - rg.y); regsum += (d <= th) ? 4.5f * d * d : d - c2;
            d = fabsf(t2 - rg.z); regsum += (d <= th) ? 4.5f * d * d : d - c2;
            d = fabsf(t3 - rg.w); regsum += (d <= th) ? 4.5f * d * d : d - c2;
        }
    }
    __syncthreads();

    // ---- Phase B: focal classification loss over the slice ----
    const float4* base = reinterpret_cast<const float4*>(
        cls + ((size_t)b * A + a0) * C);
    const int n4 = (nA * C) >> 2;   // C % 4 == 0

    float clssum = 0.0f;
    if (C == 80) {
        float sum0 = 0.0f, sum1 = 0.0f;
        int idx = tid;
        // main unrolled-by-4 loop: batch 4 independent loads for MLP
        for (; idx + 3 * NTHR < n4; idx += 4 * NTHR) {
            float4 v0 = base[idx];
            float4 v1 = base[idx + NTHR];
            float4 v2 = base[idx + 2 * NTHR];
            float4 v3 = base[idx + 3 * NTHR];
            int o0 = idx << 2,             a_0 = o0 / 80;
            int o1 = (idx + NTHR) << 2,    a_1 = o1 / 80;
            int o2 = (idx + 2*NTHR) << 2,  a_2 = o2 / 80;
            int o3 = (idx + 3*NTHR) << 2,  a_3 = o3 / 80;
            unsigned char k0 = s_code[a_0], k1 = s_code[a_1];
            unsigned char k2 = s_code[a_2], k3 = s_code[a_3];
            if (k0 != 255) sum0 += focal4(v0, k0, o0 - a_0 * 80);
            if (k1 != 255) sum1 += focal4(v1, k1, o1 - a_1 * 80);
            if (k2 != 255) sum0 += focal4(v2, k2, o2 - a_2 * 80);
            if (k3 != 255) sum1 += focal4(v3, k3, o3 - a_3 * 80);
        }
        for (; idx < n4; idx += NTHR) {
            int o = idx << 2, aa = o / 80;
            unsigned char k = s_code[aa];
            if (k != 255) sum0 += focal4(base[idx], k, o - aa * 80);
        }
        clssum = sum0 + sum1;
    } else {
        for (int idx = tid; idx < n4; idx += NTHR) {
            int o = idx << 2, aa = o / C;
            unsigned char k = s_code[aa];
            if (k != 255) clssum += focal4(base[idx], k, o - aa * C);
        }
    }

    // ---- block reduce (clssum, regsum, poscnt) ----
    #pragma unroll
    for (int off = 16; off > 0; off >>= 1) {
        clssum += __shfl_down_sync(0xFFFFFFFFu, clssum, off);
        regsum += __shfl_down_sync(0xFFFFFFFFu, regsum, off);
        poscnt += __shfl_down_sync(0xFFFFFFFFu, poscnt, off);
    }
    int lane = tid & 31, warp = tid >> 5;
    __shared__ float sw_r[8];
    if (lane == 0) { sw_f[warp] = clssum; sw_r[warp] = regsum; sw_i[warp] = poscnt; }
    __syncthreads();
    if (warp == 0) {
        float cs = (lane < NTHR / 32) ? sw_f[lane] : 0.0f;
        float rs = (lane < NTHR / 32) ? sw_r[lane] : 0.0f;
        int   pc = (lane < NTHR / 32) ? sw_i[lane] : 0;
        #pragma unroll
        for (int off = 4; off > 0; off >>= 1) {
            cs += __shfl_down_sync(0xFFFFFFFFu, cs, off);
            rs += __shfl_down_sync(0xFFFFFFFFu, rs, off);
            pc += __shfl_down_sync(0xFFFFFFFFu, pc, off);
        }
        if (lane == 0) {
            atomicAdd(&g_cls_sum[b], (double)cs);
            if (rs != 0.0f) atomicAdd(&g_reg_sum[b], (double)rs);
            if (pc != 0)    atomicAdd(&g_pos_cnt[b], pc);
            __threadfence();
            int prev = atomicAdd(&g_done, 1);
            s_last = (prev == total_blocks - 1) ? 1 : 0;
        }
    }
    __syncthreads();

    // ---- last block: finalize + reset accumulators ----
    if (s_last) {
        __threadfence();
        if (warp == 0) {
            double cm = 0.0, rm = 0.0;
            if (lane < B) {
                // volatile reads bypass L1 so we see all blocks' L2 atomics
                double cv = *((volatile double*)&g_cls_sum[lane]);
                double rv = *((volatile double*)&g_reg_sum[lane]);
                int    pv = *((volatile int*)&g_pos_cnt[lane]);
                double np = (double)pv;
                cm = cv / fmax(np, 1.0);
                rm = (pv > 0) ? rv / fmax(np * 4.0, 1.0) : 0.0;
            }
            #pragma unroll
            for (int off = 16; off > 0; off >>= 1) {
                cm += __shfl_down_sync(0xFFFFFFFFu, cm, off);
                rm += __shfl_down_sync(0xFFFFFFFFu, rm, off);
            }
            if (lane == 0) {
                out[0] = (float)(cm / (double)B);
                out[1] = (float)(rm / (double)B);
                g_done = 0;
            }
            if (lane < B) {
                g_cls_sum[lane] = 0.0;
                g_reg_sum[lane] = 0.0;
                g_pos_cnt[lane] = 0;
            }
        }
    }
}

// ---------------------------------------------------------------------------
extern "C" void kernel_launch(void* const* d_in, const int* in_sizes, int n_in,
                              void* d_out, int out_size)
{
    const float* classifications = (const float*)d_in[0];  // [B,A,C]
    const float* regressions     = (const float*)d_in[1];  // [B,A,4]
    const float* anchors         = (const float*)d_in[2];  // [1,A,4]
    const float* annotations     = (const float*)d_in[3];  // [B,M,5]
    float* out = (float*)d_out;

    const int A = in_sizes[2] / 4;
    const int B = in_sizes[1] / (4 * A);
    const int C = in_sizes[0] / (B * A);
    const int M = in_sizes[3] / (5 * B);

    const int bx = (A + ABLK - 1) / ABLK;
    dim3 grid(bx, B);
    focal_fused_kernel<<<grid, NTHR>>>(classifications, regressions, anchors,
                                       annotations, out, A, C, M, B, bx * B);
    (void)n_in; (void)out_size;
}

// round 5
// speedup vs baseline: 1.6854x; 1.1461x over previous
#include <cuda_runtime.h>
#include <cstdint>

// ---------------------------------------------------------------------------
// FocalLoss (RetinaNet), fused single kernel, issue-optimized stream.
// B=8, A=65536, C=80, M=32. ALPHA=0.5 => alpha factor identical on both
// branches, so the whole classification stream runs the NEGATIVE formula
//   0.5 * p^2 * (-ln(1-p))
// weighted per-anchor by w in {0 (ignore), -0.5*ln2 (valid)}, and each
// positive anchor gets a scalar fix-up for its single true class.
//
// Block: 512 anchors, 320 threads (16 anchors x 20 float4 per pass), so the
// float4 stream index idx = tid + 320k is contiguous AND the anchor index is
// tid/20 + 16k (no division in the loop).
// ---------------------------------------------------------------------------

#define MAX_B   8
#define MAX_M   64
#define ABLK    512
#define NTHR    320
#define NWARP   (NTHR / 32)

__device__ double g_cls_sum[MAX_B];
__device__ double g_reg_sum[MAX_B];
__device__ int    g_pos_cnt[MAX_B];
__device__ int    g_done;

__device__ __forceinline__ float lg2f(float x) {
    float r;
    asm("lg2.approx.f32 %0, %1;" : "=f"(r) : "f"(x));
    return r;
}

// neg-formula partial for one float4: sum_j p^2 * lg2(1-p)  (unweighted)
__device__ __forceinline__ float neg4(float4 v) {
    const float HI = 1.0f - 1e-4f;
    float p0 = fminf(v.x, HI), p1 = fminf(v.y, HI);
    float p2 = fminf(v.z, HI), p3 = fminf(v.w, HI);
    float l0 = lg2f(1.0f - p0), l1 = lg2f(1.0f - p1);
    float l2 = lg2f(1.0f - p2), l3 = lg2f(1.0f - p3);
    float s0 = fmaf(p0 * p0, l0, p1 * p1 * l1);
    float s1 = fmaf(p2 * p2, l2, p3 * p3 * l3);
    return s0 + s1;
}

__global__ void __launch_bounds__(NTHR)
focal_fused_kernel(const float* __restrict__ cls,         // [B,A,C]
                   const float* __restrict__ regressions, // [B,A,4]
                   const float* __restrict__ anchors,     // [A,4]
                   const float* __restrict__ annotations, // [B,M,5]
                   float* __restrict__ out,
                   int A, int C, int M, int B, int total_blocks)
{
    const int b    = blockIdx.y;
    const int a0   = blockIdx.x * ABLK;
    const int tid  = threadIdx.x;
    const int aend = min(a0 + ABLK, A);
    const int nA   = aend - a0;

    const float NEG_W = -0.34657359027997264f;   // -0.5 * ln(2)

    __shared__ float s_ann[MAX_M * 5];
    __shared__ float s_area[MAX_M];
    __shared__ float s_w[ABLK];                  // 0 = ignore, NEG_W = valid
    __shared__ float sw_c[NWARP], sw_r[NWARP];
    __shared__ int   sw_i[NWARP];
    __shared__ int   s_last;

    // ---- load annotations ----
    for (int i = tid; i < M * 5; i += NTHR)
        s_ann[i] = annotations[(size_t)b * M * 5 + i];
    __syncthreads();
    if (tid < M) {
        float x1 = s_ann[tid * 5 + 0], y1 = s_ann[tid * 5 + 1];
        float x2 = s_ann[tid * 5 + 2], y2 = s_ann[tid * 5 + 3];
        s_area[tid] = (x2 - x1) * (y2 - y1);
    }
    __syncthreads();

    // ---- Phase A: assignment, reg loss, positive fix-ups ----
    float regsum = 0.0f;   // smooth-L1 sum
    float fixsum = 0.0f;   // classification fix-up for positive true classes
    int   poscnt = 0;

    for (int la = tid; la < nA; la += NTHR) {
        const int a = a0 + la;
        float4 an = reinterpret_cast<const float4*>(anchors)[a];
        float aw = an.z - an.x;
        float ah = an.w - an.y;
        float area_a = aw * ah;

        float best = -1.0f;
        int   bi   = 0;
        #pragma unroll 8
        for (int m = 0; m < M; m++) {
            float bx1 = s_ann[m * 5 + 0], by1 = s_ann[m * 5 + 1];
            float bx2 = s_ann[m * 5 + 2], by2 = s_ann[m * 5 + 3];
            float iw = fmaxf(fminf(an.z, bx2) - fmaxf(an.x, bx1), 0.0f);
            float ih = fmaxf(fminf(an.w, by2) - fmaxf(an.y, by1), 0.0f);
            float inter = iw * ih;
            float ua    = fmaxf(area_a + s_area[m] - inter, 1e-8f);
            float iou   = inter / ua;
            if (iou > best) { best = iou; bi = m; }   // first-max (jnp.argmax)
        }

        bool pos = (best >= 0.5f);
        bool ign = (!pos) && (best >= 0.4f);
        s_w[la] = ign ? 0.0f : NEG_W;

        if (pos) {
            poscnt++;
            // ---- regression loss ----
            float gx1 = s_ann[bi * 5 + 0], gy1 = s_ann[bi * 5 + 1];
            float gx2 = s_ann[bi * 5 + 2], gy2 = s_ann[bi * 5 + 3];
            float gw = gx2 - gx1, gh = gy2 - gy1;
            float gcx = gx1 + 0.5f * gw, gcy = gy1 + 0.5f * gh;  // unclamped ctr
            gw = fmaxf(gw, 1.0f);
            gh = fmaxf(gh, 1.0f);
            float acx = an.x + 0.5f * aw, acy = an.y + 0.5f * ah;
            float t0 = (gcx - acx) / aw * 10.0f;
            float t1 = (gcy - acy) / ah * 10.0f;
            float t2 = __logf(gw / aw) * 5.0f;
            float t3 = __logf(gh / ah) * 5.0f;

            float4 rg = reinterpret_cast<const float4*>(regressions)[(size_t)b * A + a];
            const float th = 1.0f / 9.0f;
            const float c2 = 0.5f / 9.0f;
            float d;
            d = fabsf(t0 - rg.x); regsum += (d <= th) ? 4.5f * d * d : d - c2;
            d = fabsf(t1 - rg.y); regsum += (d <= th) ? 4.5f * d * d : d - c2;
            d = fabsf(t2 - rg.z); regsum += (d <= th) ? 4.5f * d * d : d - c2;
            d = fabsf(t3 - rg.w); regsum += (d <= th) ? 4.5f * d * d : d - c2;

            // ---- classification fix-up for the true class ----
            int label = (int)s_ann[bi * 5 + 4];
            float v  = cls[((size_t)b * A + a) * C + label];
            // subtract what the stream will add (identical computation)
            float ps = fminf(v, 1.0f - 1e-4f);
            fixsum -= NEG_W * (ps * ps * lg2f(1.0f - ps));
            // add the positive term with full clamp
            float pp = fminf(fmaxf(v, 1e-4f), 1.0f - 1e-4f);
            float qq = 1.0f - pp;
            fixsum += 0.5f * qq * qq * (-__logf(pp));
        }
    }
    __syncthreads();

    // ---- Phase B: weighted negative-formula stream ----
    const float4* base = reinterpret_cast<const float4*>(
        cls + ((size_t)b * A + a0) * C);

    float clssum = fixsum;

    if (C == 80 && nA == ABLK) {
        // 512 anchors * 20 float4 = 10240 float4s; 320 threads -> 32 steps.
        const int q0 = tid / 20;          // anchor of this thread at k=0
        float acc0 = 0.0f, acc1 = 0.0f;
        int idx = tid;
        int la  = q0;
        #pragma unroll 4
        for (int k = 0; k < 32; k += 2) {
            float4 v0 = base[idx];
            float4 v1 = base[idx + NTHR];
            float  w0 = s_w[la];
            float  w1 = s_w[la + 16];
            acc0 = fmaf(neg4(v0), w0, acc0);
            acc1 = fmaf(neg4(v1), w1, acc1);
            idx += 2 * NTHR;
            la  += 32;
        }
        clssum += acc0 + acc1;
    } else {
        // generic fallback (C % 4 == 0)
        const int n4 = (nA * C) >> 2;
        for (int idx = tid; idx < n4; idx += NTHR) {
            int aa = (idx << 2) / C;
            clssum = fmaf(neg4(base[idx]), s_w[aa], clssum);
        }
    }

    // ---- block reduce ----
    #pragma unroll
    for (int off = 16; off > 0; off >>= 1) {
        clssum += __shfl_down_sync(0xFFFFFFFFu, clssum, off);
        regsum += __shfl_down_sync(0xFFFFFFFFu, regsum, off);
        poscnt += __shfl_down_sync(0xFFFFFFFFu, poscnt, off);
    }
    int lane = tid & 31, warp = tid >> 5;
    if (lane == 0) { sw_c[warp] = clssum; sw_r[warp] = regsum; sw_i[warp] = poscnt; }
    __syncthreads();
    if (warp == 0) {
        float cs = (lane < NWARP) ? sw_c[lane] : 0.0f;
        float rs = (lane < NWARP) ? sw_r[lane] : 0.0f;
        int   pc = (lane < NWARP) ? sw_i[lane] : 0;
        #pragma unroll
        for (int off = 8; off > 0; off >>= 1) {
            cs += __shfl_down_sync(0xFFFFFFFFu, cs, off);
            rs += __shfl_down_sync(0xFFFFFFFFu, rs, off);
            pc += __shfl_down_sync(0xFFFFFFFFu, pc, off);
        }
        if (lane == 0) {
            atomicAdd(&g_cls_sum[b], (double)cs);
            if (rs != 0.0f) atomicAdd(&g_reg_sum[b], (double)rs);
            if (pc != 0)    atomicAdd(&g_pos_cnt[b], pc);
            __threadfence();
            int prev = atomicAdd(&g_done, 1);
            s_last = (prev == total_blocks - 1) ? 1 : 0;
        }
    }
    __syncthreads();

    // ---- last block: finalize + reset accumulators for next replay ----
    if (s_last) {
        __threadfence();
        if (warp == 0) {
            double cm = 0.0, rm = 0.0;
            if (lane < B) {
                double cv = *((volatile double*)&g_cls_sum[lane]);
                double rv = *((volatile double*)&g_reg_sum[lane]);
                int    pv = *((volatile int*)&g_pos_cnt[lane]);
                double np = (double)pv;
                cm = cv / fmax(np, 1.0);
                rm = (pv > 0) ? rv / fmax(np * 4.0, 1.0) : 0.0;
            }
            #pragma unroll
            for (int off = 16; off > 0; off >>= 1) {
                cm += __shfl_down_sync(0xFFFFFFFFu, cm, off);
                rm += __shfl_down_sync(0xFFFFFFFFu, rm, off);
            }
            if (lane == 0) {
                out[0] = (float)(cm / (double)B);
                out[1] = (float)(rm / (double)B);
                g_done = 0;
            }
            if (lane < B) {
                g_cls_sum[lane] = 0.0;
                g_reg_sum[lane] = 0.0;
                g_pos_cnt[lane] = 0;
            }
        }
    }
}

// ---------------------------------------------------------------------------
extern "C" void kernel_launch(void* const* d_in, const int* in_sizes, int n_in,
                              void* d_out, int out_size)
{
    const float* classifications = (const float*)d_in[0];  // [B,A,C]
    const float* regressions     = (const float*)d_in[1];  // [B,A,4]
    const float* anchors         = (const float*)d_in[2];  // [1,A,4]
    const float* annotations     = (const float*)d_in[3];  // [B,M,5]
    float* out = (float*)d_out;

    const int A = in_sizes[2] / 4;
    const int B = in_sizes[1] / (4 * A);
    const int C = in_sizes[0] / (B * A);
    const int M = in_sizes[3] / (5 * B);

    const int bx = (A + ABLK - 1) / ABLK;
    dim3 grid(bx, B);
    focal_fused_kernel<<<grid, NTHR>>>(classifications, regressions, anchors,
                                       annotations, out, A, C, M, B, bx * B);
    (void)n_in; (void)out_size;
}

// round 6
// speedup vs baseline: 2.5281x; 1.5000x over previous
#include <cuda_runtime.h>
#include <cstdint>

// ---------------------------------------------------------------------------
// FocalLoss (RetinaNet), fused single kernel.
// B=8, A=65536, C=80, M=32. ALPHA=0.5 => both focal branches share the 0.5
// alpha factor, so the stream computes only the negative formula
//   0.5 * p^2 * (-ln(1-p)) = NEG_W * p^2 * lg2(1-p),  NEG_W = -0.5*ln2
// weighted per-anchor w in {0 (ignore), NEG_W (valid)}; positives get a
// scalar fix-up for their single true class in phase A.
// Phase A argmax is DIVISION-FREE (cross-multiplied IoU compare) because the
// harness builds without fast-math (fp32 div is ~10+ instructions).
// Stream math uses packed f32x2 (fma.rn.f32x2 / mul.rn.f32x2).
// Block: 512 anchors, 320 threads (idx = tid + 320k contiguous; anchor =
// tid/20 + 16k, no division in the loop).
// ---------------------------------------------------------------------------

#define MAX_B   8
#define MAX_M   64
#define ABLK    512
#define NTHR    320
#define NWARP   (NTHR / 32)

__device__ double g_cls_sum[MAX_B];
__device__ double g_reg_sum[MAX_B];
__device__ int    g_pos_cnt[MAX_B];
__device__ int    g_done;

__device__ __forceinline__ float lg2f(float x) {
    float r;
    asm("lg2.approx.f32 %0, %1;" : "=f"(r) : "f"(x));
    return r;
}

typedef unsigned long long ull;

__device__ __forceinline__ ull pack2(float lo, float hi) {
    ull r; asm("mov.b64 %0, {%1, %2};" : "=l"(r) : "f"(lo), "f"(hi)); return r;
}
__device__ __forceinline__ void unpack2(ull v, float& lo, float& hi) {
    asm("mov.b64 {%0, %1}, %2;" : "=f"(lo), "=f"(hi) : "l"(v));
}
__device__ __forceinline__ ull fma2(ull a, ull b, ull c) {
    ull r; asm("fma.rn.f32x2 %0, %1, %2, %3;" : "=l"(r) : "l"(a), "l"(b), "l"(c)); return r;
}
__device__ __forceinline__ ull mul2(ull a, ull b) {
    ull r; asm("mul.rn.f32x2 %0, %1, %2;" : "=l"(r) : "l"(a), "l"(b)); return r;
}

// accumulate w * p^2 * lg2(1-p) for 4 elements into packed acc
__device__ __forceinline__ void neg4_acc(float4 v, ull w2, ull& acc,
                                         ull NEG1, ull ONE2) {
    const float HI = 1.0f - 1e-4f;
    float p0 = fminf(v.x, HI), p1 = fminf(v.y, HI);
    float p2 = fminf(v.z, HI), p3 = fminf(v.w, HI);
    ull P01 = pack2(p0, p1), P23 = pack2(p2, p3);
    ull Q01 = fma2(P01, NEG1, ONE2);        // 1 - p
    ull Q23 = fma2(P23, NEG1, ONE2);
    float q0, q1, q2, q3;
    unpack2(Q01, q0, q1); unpack2(Q23, q2, q3);
    ull L01 = pack2(lg2f(q0), lg2f(q1));
    ull L23 = pack2(lg2f(q2), lg2f(q3));
    ull T01 = mul2(P01, P01), T23 = mul2(P23, P23);
    ull M01 = mul2(T01, L01), M23 = mul2(T23, L23);
    acc = fma2(M01, w2, acc);
    acc = fma2(M23, w2, acc);
}

__global__ void __launch_bounds__(NTHR)
focal_fused_kernel(const float* __restrict__ cls,         // [B,A,C]
                   const float* __restrict__ regressions, // [B,A,4]
                   const float* __restrict__ anchors,     // [A,4]
                   const float* __restrict__ annotations, // [B,M,5]
                   float* __restrict__ out,
                   int A, int C, int M, int B, int total_blocks)
{
    const int b    = blockIdx.y;
    const int a0   = blockIdx.x * ABLK;
    const int tid  = threadIdx.x;
    const int aend = min(a0 + ABLK, A);
    const int nA   = aend - a0;

    const float NEG_W = -0.34657359027997264f;   // -0.5 * ln(2)

    __shared__ float s_ann[MAX_M * 5];
    __shared__ float s_area[MAX_M];
    __shared__ float s_w[ABLK];                  // 0 = ignore, NEG_W = valid
    __shared__ float sw_c[NWARP], sw_r[NWARP];
    __shared__ int   sw_i[NWARP];
    __shared__ int   s_last;

    // ---- load annotations ----
    for (int i = tid; i < M * 5; i += NTHR)
        s_ann[i] = annotations[(size_t)b * M * 5 + i];
    __syncthreads();
    if (tid < M) {
        float x1 = s_ann[tid * 5 + 0], y1 = s_ann[tid * 5 + 1];
        float x2 = s_ann[tid * 5 + 2], y2 = s_ann[tid * 5 + 3];
        s_area[tid] = (x2 - x1) * (y2 - y1);
    }
    __syncthreads();

    // ---- Phase A: division-free assignment, reg loss, positive fix-ups ----
    float regsum = 0.0f;
    float fixsum = 0.0f;
    int   poscnt = 0;

    for (int la = tid; la < nA; la += NTHR) {
        const int a = a0 + la;
        float4 an = reinterpret_cast<const float4*>(anchors)[a];
        float aw = an.z - an.x;
        float ah = an.w - an.y;
        float area_a = aw * ah;

        // m = 0 init
        float bin, bua;   // best inter / best ua
        int   bi = 0;
        {
            float iw = fmaxf(fminf(an.z, s_ann[2]) - fmaxf(an.x, s_ann[0]), 0.0f);
            float ih = fmaxf(fminf(an.w, s_ann[3]) - fmaxf(an.y, s_ann[1]), 0.0f);
            bin = iw * ih;
            bua = fmaxf(area_a + s_area[0] - bin, 1e-8f);
        }
        #pragma unroll 8
        for (int m = 1; m < M; m++) {
            float bx1 = s_ann[m * 5 + 0], by1 = s_ann[m * 5 + 1];
            float bx2 = s_ann[m * 5 + 2], by2 = s_ann[m * 5 + 3];
            float iw = fmaxf(fminf(an.z, bx2) - fmaxf(an.x, bx1), 0.0f);
            float ih = fmaxf(fminf(an.w, by2) - fmaxf(an.y, by1), 0.0f);
            float inter = iw * ih;
            float ua    = fmaxf(area_a + s_area[m] - inter, 1e-8f);
            // iou_m > iou_best  <=>  inter*bua > bin*ua   (ua, bua > 0)
            if (inter * bua > bin * ua) { bi = m; bin = inter; bua = ua; }
        }

        bool pos = (bin >= 0.5f * bua);
        bool ign = (!pos) && (bin >= 0.4f * bua);
        s_w[la] = ign ? 0.0f : NEG_W;

        if (pos) {
            poscnt++;
            // ---- regression loss ----
            float gx1 = s_ann[bi * 5 + 0], gy1 = s_ann[bi * 5 + 1];
            float gx2 = s_ann[bi * 5 + 2], gy2 = s_ann[bi * 5 + 3];
            float gw = gx2 - gx1, gh = gy2 - gy1;
            float gcx = gx1 + 0.5f * gw, gcy = gy1 + 0.5f * gh;  // unclamped ctr
            gw = fmaxf(gw, 1.0f);
            gh = fmaxf(gh, 1.0f);
            float acx = an.x + 0.5f * aw, acy = an.y + 0.5f * ah;
            float t0 = __fdividef(gcx - acx, aw) * 10.0f;
            float t1 = __fdividef(gcy - acy, ah) * 10.0f;
            float t2 = __logf(__fdividef(gw, aw)) * 5.0f;
            float t3 = __logf(__fdividef(gh, ah)) * 5.0f;

            float4 rg = reinterpret_cast<const float4*>(regressions)[(size_t)b * A + a];
            const float th = 1.0f / 9.0f;
            const float c2 = 0.5f / 9.0f;
            float d;
            d = fabsf(t0 - rg.x); regsum += (d <= th) ? 4.5f * d * d : d - c2;
            d = fabsf(t1 - rg.y); regsum += (d <= th) ? 4.5f * d * d : d - c2;
            d = fabsf(t2 - rg.z); regsum += (d <= th) ? 4.5f * d * d : d - c2;
            d = fabsf(t3 - rg.w); regsum += (d <= th) ? 4.5f * d * d : d - c2;

            // ---- classification fix-up for the true class ----
            int label = (int)s_ann[bi * 5 + 4];
            float v  = cls[((size_t)b * A + a) * C + label];
            // subtract what the stream will add (same math as neg4_acc)
            float ps = fminf(v, 1.0f - 1e-4f);
            float qs = 1.0f - ps;
            fixsum -= NEG_W * (ps * ps * lg2f(qs));
            // add the positive term with full clamp
            float pp = fminf(fmaxf(v, 1e-4f), 1.0f - 1e-4f);
            float qq = 1.0f - pp;
            fixsum += 0.5f * qq * qq * (-__logf(pp));
        }
    }
    __syncthreads();

    // ---- Phase B: weighted negative-formula stream (packed f32x2) ----
    const float4* base = reinterpret_cast<const float4*>(
        cls + ((size_t)b * A + a0) * C);

    float clssum = fixsum;
    const ull NEG1 = pack2(-1.0f, -1.0f);
    const ull ONE2 = pack2(1.0f, 1.0f);

    if (C == 80 && nA == ABLK) {
        // 512 anchors * 20 float4 = 10240 float4s; 320 threads -> 32 steps.
        ull accA = pack2(0.0f, 0.0f);
        ull accB = pack2(0.0f, 0.0f);
        int idx = tid;
        int la  = tid / 20;
        #pragma unroll 4
        for (int k = 0; k < 32; k += 2) {
            float4 v0 = base[idx];
            float4 v1 = base[idx + NTHR];
            ull w0 = pack2(s_w[la],      s_w[la]);
            ull w1 = pack2(s_w[la + 16], s_w[la + 16]);
            neg4_acc(v0, w0, accA, NEG1, ONE2);
            neg4_acc(v1, w1, accB, NEG1, ONE2);
            idx += 2 * NTHR;
            la  += 32;
        }
        float aLo, aHi, bLo, bHi;
        unpack2(accA, aLo, aHi);
        unpack2(accB, bLo, bHi);
        clssum += (aLo + aHi) + (bLo + bHi);
    } else {
        // generic fallback (C % 4 == 0)
        const int n4 = (nA * C) >> 2;
        ull acc = pack2(0.0f, 0.0f);
        for (int idx = tid; idx < n4; idx += NTHR) {
            int aa = (idx << 2) / C;
            ull w2 = pack2(s_w[aa], s_w[aa]);
            neg4_acc(base[idx], w2, acc, NEG1, ONE2);
        }
        float lo, hi; unpack2(acc, lo, hi);
        clssum += lo + hi;
    }

    // ---- block reduce ----
    #pragma unroll
    for (int off = 16; off > 0; off >>= 1) {
        clssum += __shfl_down_sync(0xFFFFFFFFu, clssum, off);
        regsum += __shfl_down_sync(0xFFFFFFFFu, regsum, off);
        poscnt += __shfl_down_sync(0xFFFFFFFFu, poscnt, off);
    }
    int lane = tid & 31, warp = tid >> 5;
    if (lane == 0) { sw_c[warp] = clssum; sw_r[warp] = regsum; sw_i[warp] = poscnt; }
    __syncthreads();
    if (warp == 0) {
        float cs = (lane < NWARP) ? sw_c[lane] : 0.0f;
        float rs = (lane < NWARP) ? sw_r[lane] : 0.0f;
        int   pc = (lane < NWARP) ? sw_i[lane] : 0;
        #pragma unroll
        for (int off = 8; off > 0; off >>= 1) {
            cs += __shfl_down_sync(0xFFFFFFFFu, cs, off);
            rs += __shfl_down_sync(0xFFFFFFFFu, rs, off);
            pc += __shfl_down_sync(0xFFFFFFFFu, pc, off);
        }
        if (lane == 0) {
            atomicAdd(&g_cls_sum[b], (double)cs);
            if (rs != 0.0f) atomicAdd(&g_reg_sum[b], (double)rs);
            if (pc != 0)    atomicAdd(&g_pos_cnt[b], pc);
            __threadfence();
            int prev = atomicAdd(&g_done, 1);
            s_last = (prev == total_blocks - 1) ? 1 : 0;
        }
    }
    __syncthreads();

    // ---- last block: finalize + reset accumulators for next replay ----
    if (s_last) {
        __threadfence();
        if (warp == 0) {
            double cm = 0.0, rm = 0.0;
            if (lane < B) {
                double cv = *((volatile double*)&g_cls_sum[lane]);
                double rv = *((volatile double*)&g_reg_sum[lane]);
                int    pv = *((volatile int*)&g_pos_cnt[lane]);
                double np = (double)pv;
                cm = cv / fmax(np, 1.0);
                rm = (pv > 0) ? rv / fmax(np * 4.0, 1.0) : 0.0;
            }
            #pragma unroll
            for (int off = 16; off > 0; off >>= 1) {
                cm += __shfl_down_sync(0xFFFFFFFFu, cm, off);
                rm += __shfl_down_sync(0xFFFFFFFFu, rm, off);
            }
            if (lane == 0) {
                out[0] = (float)(cm / (double)B);
                out[1] = (float)(rm / (double)B);
                g_done = 0;
            }
            if (lane < B) {
                g_cls_sum[lane] = 0.0;
                g_reg_sum[lane] = 0.0;
                g_pos_cnt[lane] = 0;
            }
        }
    }
}

// ---------------------------------------------------------------------------
extern "C" void kernel_launch(void* const* d_in, const int* in_sizes, int n_in,
                              void* d_out, int out_size)
{
    const float* classifications = (const float*)d_in[0];  // [B,A,C]
    const float* regressions     = (const float*)d_in[1];  // [B,A,4]
    const float* anchors         = (const float*)d_in[2];  // [1,A,4]
    const float* annotations     = (const float*)d_in[3];  // [B,M,5]
    float* out = (float*)d_out;

    const int A = in_sizes[2] / 4;
    const int B = in_sizes[1] / (4 * A);
    const int C = in_sizes[0] / (B * A);
    const int M = in_sizes[3] / (5 * B);

    const int bx = (A + ABLK - 1) / ABLK;
    dim3 grid(bx, B);
    focal_fused_kernel<<<grid, NTHR>>>(classifications, regressions, anchors,
                                       annotations, out, A, C, M, B, bx * B);
    (void)n_in; (void)out_size;
}

// round 7
// speedup vs baseline: 2.6471x; 1.0471x over previous
#include <cuda_runtime.h>
#include <cstdint>

// ---------------------------------------------------------------------------
// FocalLoss (RetinaNet), fused single kernel.
// B=8, A=65536, C=80, M=32. ALPHA=0.5 => both focal branches share the 0.5
// factor, so the stream computes only the negative formula
//   0.5 * p^2 * (-ln(1-p)) = NEG_W * p^2 * lg2(1-p),  NEG_W = -0.5*ln2
// with clamp folded into the log:  max(lg2(1-v), lg2(1e-4)),  and p^2 -> v^2
// (identical except v > 1-1e-4, total error ~1e-8, mirrored in the fix-up).
// Weight per anchor w in {0 (ignore), NEG_W (valid)}; positives get a scalar
// fix-up for their true class in phase A.
// Phase A: division-free argmax (cross-multiplied IoU compare), boxes stored
// as float4 in smem (LDS.128).
// Stream: ulonglong2 loads => f32x2 operands with zero pack cost; 4 loads in
// flight. Block: 512 anchors, 320 threads (idx = tid + 320k contiguous;
// anchor = tid/20 + 16k, no division in the loop).
// ---------------------------------------------------------------------------

#define MAX_B   8
#define MAX_M   64
#define ABLK    512
#define NTHR    320
#define NWARP   (NTHR / 32)

__device__ double g_cls_sum[MAX_B];
__device__ double g_reg_sum[MAX_B];
__device__ int    g_pos_cnt[MAX_B];
__device__ int    g_done;

__device__ __forceinline__ float lg2f(float x) {
    float r;
    asm("lg2.approx.f32 %0, %1;" : "=f"(r) : "f"(x));
    return r;
}

typedef unsigned long long ull;

__device__ __forceinline__ ull pack2(float lo, float hi) {
    ull r; asm("mov.b64 %0, {%1, %2};" : "=l"(r) : "f"(lo), "f"(hi)); return r;
}
__device__ __forceinline__ void unpack2(ull v, float& lo, float& hi) {
    asm("mov.b64 {%0, %1}, %2;" : "=f"(lo), "=f"(hi) : "l"(v));
}
__device__ __forceinline__ ull fma2(ull a, ull b, ull c) {
    ull r; asm("fma.rn.f32x2 %0, %1, %2, %3;" : "=l"(r) : "l"(a), "l"(b), "l"(c)); return r;
}
__device__ __forceinline__ ull mul2(ull a, ull b) {
    ull r; asm("mul.rn.f32x2 %0, %1, %2;" : "=l"(r) : "l"(a), "l"(b)); return r;
}

#define LCL  (-13.28771237954945f)   /* lg2(1e-4) */

// acc += wgt2 * v^2 * max(lg2(1-v), LCL) for 4 elements (packed pairs)
__device__ __forceinline__ void neg4_acc(ull w01, ull w23, ull wgt2,
                                         ull& acc0, ull& acc1,
                                         ull NEG1, ull ONE2) {
    ull q01 = fma2(w01, NEG1, ONE2);     // 1 - v  (exact, same as FADD)
    ull q23 = fma2(w23, NEG1, ONE2);
    float q0, q1, q2, q3;
    unpack2(q01, q0, q1); unpack2(q23, q2, q3);
    float l0 = fmaxf(lg2f(q0), LCL), l1 = fmaxf(lg2f(q1), LCL);
    float l2 = fmaxf(lg2f(q2), LCL), l3 = fmaxf(lg2f(q3), LCL);
    ull L01 = pack2(l0, l1), L23 = pack2(l2, l3);
    ull t01 = mul2(w01, w01), t23 = mul2(w23, w23);
    acc0 = fma2(mul2(t01, L01), wgt2, acc0);
    acc1 = fma2(mul2(t23, L23), wgt2, acc1);
}

__global__ void __launch_bounds__(NTHR)
focal_fused_kernel(const float* __restrict__ cls,         // [B,A,C]
                   const float* __restrict__ regressions, // [B,A,4]
                   const float* __restrict__ anchors,     // [A,4]
                   const float* __restrict__ annotations, // [B,M,5]
                   float* __restrict__ out,
                   int A, int C, int M, int B, int total_blocks)
{
    const int b    = blockIdx.y;
    const int a0   = blockIdx.x * ABLK;
    const int tid  = threadIdx.x;
    const int aend = min(a0 + ABLK, A);
    const int nA   = aend - a0;

    const float NEG_W = -0.34657359027997264f;   // -0.5 * ln(2)

    __shared__ float4 s_box[MAX_M];              // x1,y1,x2,y2
    __shared__ float  s_area[MAX_M];
    __shared__ float  s_lab[MAX_M];
    __shared__ float  s_w[ABLK];                 // 0 = ignore, NEG_W = valid
    __shared__ float  sw_c[NWARP], sw_r[NWARP];
    __shared__ int    sw_i[NWARP];
    __shared__ int    s_last;

    // ---- load annotations -> float4 boxes + area + label ----
    if (tid < M) {
        const float* an = annotations + (size_t)b * M * 5 + tid * 5;
        float x1 = an[0], y1 = an[1], x2 = an[2], y2 = an[3];
        s_box[tid]  = make_float4(x1, y1, x2, y2);
        s_area[tid] = (x2 - x1) * (y2 - y1);
        s_lab[tid]  = an[4];
    }
    __syncthreads();

    // ---- Phase A: division-free assignment, reg loss, positive fix-ups ----
    float regsum = 0.0f;
    float fixsum = 0.0f;
    int   poscnt = 0;

    for (int la = tid; la < nA; la += NTHR) {
        const int a = a0 + la;
        float4 an = reinterpret_cast<const float4*>(anchors)[a];
        float aw = an.z - an.x;
        float ah = an.w - an.y;
        float area_a = aw * ah;

        float bin, bua;   // best inter / best union
        int   bi = 0;
        {
            float4 bx = s_box[0];
            float iw = fmaxf(fminf(an.z, bx.z) - fmaxf(an.x, bx.x), 0.0f);
            float ih = fmaxf(fminf(an.w, bx.w) - fmaxf(an.y, bx.y), 0.0f);
            bin = iw * ih;
            bua = fmaxf(area_a + s_area[0] - bin, 1e-8f);
        }
        #pragma unroll 8
        for (int m = 1; m < M; m++) {
            float4 bx = s_box[m];
            float iw = fmaxf(fminf(an.z, bx.z) - fmaxf(an.x, bx.x), 0.0f);
            float ih = fmaxf(fminf(an.w, bx.w) - fmaxf(an.y, bx.y), 0.0f);
            float inter = iw * ih;
            float ua    = fmaxf(area_a + s_area[m] - inter, 1e-8f);
            // iou_m > iou_best  <=>  inter*bua > bin*ua   (ua, bua > 0)
            if (inter * bua > bin * ua) { bi = m; bin = inter; bua = ua; }
        }

        bool pos = (bin >= 0.5f * bua);
        bool ign = (!pos) && (bin >= 0.4f * bua);
        s_w[la] = ign ? 0.0f : NEG_W;

        if (pos) {
            poscnt++;
            // ---- regression loss ----
            float4 gb = s_box[bi];
            float gw = gb.z - gb.x, gh = gb.w - gb.y;
            float gcx = gb.x + 0.5f * gw, gcy = gb.y + 0.5f * gh;  // unclamped
            gw = fmaxf(gw, 1.0f);
            gh = fmaxf(gh, 1.0f);
            float acx = an.x + 0.5f * aw, acy = an.y + 0.5f * ah;
            float t0 = __fdividef(gcx - acx, aw) * 10.0f;
            float t1 = __fdividef(gcy - acy, ah) * 10.0f;
            float t2 = __logf(__fdividef(gw, aw)) * 5.0f;
            float t3 = __logf(__fdividef(gh, ah)) * 5.0f;

            float4 rg = reinterpret_cast<const float4*>(regressions)[(size_t)b * A + a];
            const float th = 1.0f / 9.0f;
            const float c2 = 0.5f / 9.0f;
            float d;
            d = fabsf(t0 - rg.x); regsum += (d <= th) ? 4.5f * d * d : d - c2;
            d = fabsf(t1 - rg.y); regsum += (d <= th) ? 4.5f * d * d : d - c2;
            d = fabsf(t2 - rg.z); regsum += (d <= th) ? 4.5f * d * d : d - c2;
            d = fabsf(t3 - rg.w); regsum += (d <= th) ? 4.5f * d * d : d - c2;

            // ---- classification fix-up for the true class ----
            int label = (int)s_lab[bi];
            float v  = cls[((size_t)b * A + a) * C + label];
            // subtract exactly what the stream adds (same formula)
            fixsum -= NEG_W * (v * v * fmaxf(lg2f(1.0f - v), LCL));
            // add the positive-branch term with full clamps
            float pp = fminf(fmaxf(v, 1e-4f), 1.0f - 1e-4f);
            float qq = 1.0f - pp;
            fixsum += 0.5f * qq * qq * (-__logf(pp));
        }
    }
    __syncthreads();

    // ---- Phase B: weighted negative-formula stream (packed f32x2) ----
    float clssum = fixsum;
    const ull NEG1 = pack2(-1.0f, -1.0f);
    const ull ONE2 = pack2(1.0f, 1.0f);

    if (C == 80 && nA == ABLK) {
        // 512 anchors * 20 float4 = 10240 float4s; 320 threads -> 32 steps,
        // unrolled 4 loads in flight.
        const ulonglong2* base = reinterpret_cast<const ulonglong2*>(
            cls + ((size_t)b * A + a0) * 80);
        ull acc0 = pack2(0.0f, 0.0f), acc1 = pack2(0.0f, 0.0f);
        ull acc2 = pack2(0.0f, 0.0f), acc3 = pack2(0.0f, 0.0f);
        int idx = tid;
        int la  = tid / 20;
        #pragma unroll
        for (int k = 0; k < 8; k++) {
            ulonglong2 v0 = base[idx];
            ulonglong2 v1 = base[idx + NTHR];
            ulonglong2 v2 = base[idx + 2 * NTHR];
            ulonglong2 v3 = base[idx + 3 * NTHR];
            float w0 = s_w[la], w1 = s_w[la + 16];
            float w2 = s_w[la + 32], w3 = s_w[la + 48];
            neg4_acc(v0.x, v0.y, pack2(w0, w0), acc0, acc1, NEG1, ONE2);
            neg4_acc(v1.x, v1.y, pack2(w1, w1), acc2, acc3, NEG1, ONE2);
            neg4_acc(v2.x, v2.y, pack2(w2, w2), acc0, acc1, NEG1, ONE2);
            neg4_acc(v3.x, v3.y, pack2(w3, w3), acc2, acc3, NEG1, ONE2);
            idx += 4 * NTHR;
            la  += 64;
        }
        float s0, s1, s2, s3, s4, s5, s6, s7;
        unpack2(acc0, s0, s1); unpack2(acc1, s2, s3);
        unpack2(acc2, s4, s5); unpack2(acc3, s6, s7);
        clssum += ((s0 + s1) + (s2 + s3)) + ((s4 + s5) + (s6 + s7));
    } else {
        // generic fallback (C % 4 == 0)
        const ulonglong2* base = reinterpret_cast<const ulonglong2*>(
            cls + ((size_t)b * A + a0) * C);
        const int n4 = (nA * C) >> 2;
        ull acc0 = pack2(0.0f, 0.0f), acc1 = pack2(0.0f, 0.0f);
        for (int idx = tid; idx < n4; idx += NTHR) {
            int aa = (idx << 2) / C;
            float w = s_w[aa];
            ulonglong2 v = base[idx];
            neg4_acc(v.x, v.y, pack2(w, w), acc0, acc1, NEG1, ONE2);
        }
        float s0, s1, s2, s3;
        unpack2(acc0, s0, s1); unpack2(acc1, s2, s3);
        clssum += (s0 + s1) + (s2 + s3);
    }

    // ---- block reduce ----
    #pragma unroll
    for (int off = 16; off > 0; off >>= 1) {
        clssum += __shfl_down_sync(0xFFFFFFFFu, clssum, off);
        regsum += __shfl_down_sync(0xFFFFFFFFu, regsum, off);
        poscnt += __shfl_down_sync(0xFFFFFFFFu, poscnt, off);
    }
    int lane = tid & 31, warp = tid >> 5;
    if (lane == 0) { sw_c[warp] = clssum; sw_r[warp] = regsum; sw_i[warp] = poscnt; }
    __syncthreads();
    if (warp == 0) {
        float cs = (lane < NWARP) ? sw_c[lane] : 0.0f;
        float rs = (lane < NWARP) ? sw_r[lane] : 0.0f;
        int   pc = (lane < NWARP) ? sw_i[lane] : 0;
        #pragma unroll
        for (int off = 8; off > 0; off >>= 1) {
            cs += __shfl_down_sync(0xFFFFFFFFu, cs, off);
            rs += __shfl_down_sync(0xFFFFFFFFu, rs, off);
            pc += __shfl_down_sync(0xFFFFFFFFu, pc, off);
        }
        if (lane == 0) {
            atomicAdd(&g_cls_sum[b], (double)cs);
            if (rs != 0.0f) atomicAdd(&g_reg_sum[b], (double)rs);
            if (pc != 0)    atomicAdd(&g_pos_cnt[b], pc);
            __threadfence();
            int prev = atomicAdd(&g_done, 1);
            s_last = (prev == total_blocks - 1) ? 1 : 0;
        }
    }
    __syncthreads();

    // ---- last block: finalize + reset accumulators for next replay ----
    if (s_last) {
        __threadfence();
        if (warp == 0) {
            double cm = 0.0, rm = 0.0;
            if (lane < B) {
                double cv = *((volatile double*)&g_cls_sum[lane]);
                double rv = *((volatile double*)&g_reg_sum[lane]);
                int    pv = *((volatile int*)&g_pos_cnt[lane]);
                double np = (double)pv;
                cm = cv / fmax(np, 1.0);
                rm = (pv > 0) ? rv / fmax(np * 4.0, 1.0) : 0.0;
            }
            #pragma unroll
            for (int off = 16; off > 0; off >>= 1) {
                cm += __shfl_down_sync(0xFFFFFFFFu, cm, off);
                rm += __shfl_down_sync(0xFFFFFFFFu, rm, off);
            }
            if (lane == 0) {
                out[0] = (float)(cm / (double)B);
                out[1] = (float)(rm / (double)B);
                g_done = 0;
            }
            if (lane < B) {
                g_cls_sum[lane] = 0.0;
                g_reg_sum[lane] = 0.0;
                g_pos_cnt[lane] = 0;
            }
        }
    }
}

// ---------------------------------------------------------------------------
extern "C" void kernel_launch(void* const* d_in, const int* in_sizes, int n_in,
                              void* d_out, int out_size)
{
    const float* classifications = (const float*)d_in[0];  // [B,A,C]
    const float* regressions     = (const float*)d_in[1];  // [B,A,4]
    const float* anchors         = (const float*)d_in[2];  // [1,A,4]
    const float* annotations     = (const float*)d_in[3];  // [B,M,5]
    float* out = (float*)d_out;

    const int A = in_sizes[2] / 4;
    const int B = in_sizes[1] / (4 * A);
    const int C = in_sizes[0] / (B * A);
    const int M = in_sizes[3] / (5 * B);

    const int bx = (A + ABLK - 1) / ABLK;
    dim3 grid(bx, B);
    focal_fused_kernel<<<grid, NTHR>>>(classifications, regressions, anchors,
                                       annotations, out, A, C, M, B, bx * B);
    (void)n_in; (void)out_size;
}